// round 11
// baseline (speedup 1.0000x reference)
#include <cuda_runtime.h>
#include <cuda_bf16.h>

// NeRF render + accumulate, bit-matching XLA:CPU's ReduceWindowRewriter
// (base_length=16) radix-16 cumsum tree. PASSES @ rel_err 1.5e-7.
// R10: structure = R7 (proven 82.4us) with:
//   - k2 fused into k1 (smem fold of block's 256 l1 values -> 16 l2 values)
//   - new k4b producing l1s (scanned l1, exact k4 bracketing) so k5's prefix
//     is ONE coalesced load; k5 keeps R7's load-first, no-barrier layout.
// Rounding-critical sequences unchanged:
//   sdt_i = fmul(sigma_i, fsub(te_i, ts_i))
//   fold-left rows with fadd; c = (row0) ? acc : fadd(acc, prefix)
//   excl = fsub(c, sdt); d = fsub(excl_i, e_lead); w = fmul(exp(-d), 1-exp(-sdt))

#define MAX_S    (1 << 22)
#define N1_MAX   (MAX_S / 16)      // 262144
#define N2_MAX   (N1_MAX / 16)     // 16384
#define MAX_RAYS (1 << 18)
#define WARPS_PER_BLOCK 8
#define K6_THREADS (WARPS_PER_BLOCK * 32)

__device__ __align__(16) float g_sdt[MAX_S];
__device__ __align__(16) float g_c[MAX_S];
__device__ __align__(16) float g_l1[N1_MAX];
__device__ __align__(16) float g_l1s[N1_MAX];    // scanned l1 (k4 bracketing)
__device__ __align__(16) float g_l2[N2_MAX];     // raw row totals of l1
__device__ __align__(16) float g_l2s[N2_MAX];    // scanned l2
__device__ int   g_rs[MAX_RAYS];
__device__ int   g_re[MAX_RAYS];
__device__ float g_elead[MAX_RAYS];

// ---------------------------------------------------------------------------
// K1: sdt = fmul(sg, fsub(te, ts)); fold-left per 16-row -> g_l1; then the
// block's 256 l1 values are folded (16 at a time, same fold-left order as the
// old k2) into g_l2. Also zero-inits ray bounds.
// ---------------------------------------------------------------------------
__global__ __launch_bounds__(256)
void k1_sdt_fold(const float* __restrict__ ts,
                 const float* __restrict__ te,
                 const float* __restrict__ sg,
                 int S, int n_rays)
{
    __shared__ float sm[256];
    const int tid = threadIdx.x;
    const int r = blockIdx.x * 256 + tid;
    const int R = (S + 15) >> 4;

    for (int j = r; j < n_rays; j += gridDim.x * blockDim.x) { g_rs[j] = 0; g_re[j] = 0; }

    float acc = 0.0f;
    if (r < R) {
        const int base = r << 4;
        if (base + 16 <= S) {
            const float4* ts4 = reinterpret_cast<const float4*>(ts + base);
            const float4* te4 = reinterpret_cast<const float4*>(te + base);
            const float4* sg4 = reinterpret_cast<const float4*>(sg + base);
            float4*       sd4 = reinterpret_cast<float4*>(g_sdt + base);
            #pragma unroll
            for (int q = 0; q < 4; q++) {
                const float4 a = ts4[q], b = te4[q], s = sg4[q];
                float4 v;
                v.x = __fmul_rn(s.x, __fsub_rn(b.x, a.x));
                v.y = __fmul_rn(s.y, __fsub_rn(b.y, a.y));
                v.z = __fmul_rn(s.z, __fsub_rn(b.z, a.z));
                v.w = __fmul_rn(s.w, __fsub_rn(b.w, a.w));
                sd4[q] = v;
                acc = __fadd_rn(acc, v.x);   // exact fold-left order preserved
                acc = __fadd_rn(acc, v.y);
                acc = __fadd_rn(acc, v.z);
                acc = __fadd_rn(acc, v.w);
            }
        } else {
            const int lim = S - base;
            for (int k = 0; k < lim; k++) {
                const int i = base + k;
                const float v = __fmul_rn(sg[i], __fsub_rn(te[i], ts[i]));
                g_sdt[i] = v;
                acc = __fadd_rn(acc, v);
            }
        }
        g_l1[r] = acc;
    }

    // fused k2: fold 16 l1 values -> one l2 entry (trailing zeros are inert:
    // all sdt >= 0 so fadd(x, +0) == x bitwise).
    sm[tid] = acc;
    __syncthreads();
    if (tid < 16) {
        const int rowb = tid << 4;
        float a2 = 0.0f;
        #pragma unroll
        for (int k = 0; k < 16; k++)
            a2 = __fadd_rn(a2, sm[rowb + k]);
        g_l2[blockIdx.x * 16 + tid] = a2;
    }
}

// ---------------------------------------------------------------------------
// K3: single-CTA exact radix-16 scan: out = cum(in), n <= 16384. in stays raw.
// ---------------------------------------------------------------------------
__device__ __forceinline__ void seq_scan(float* a, int n) {
    float acc = 0.0f;
    for (int i = 0; i < n; i++) { acc = __fadd_rn(acc, a[i]); a[i] = acc; }
}

__global__ __launch_bounds__(1024)
void k3_midscan(const float* __restrict__ in, float* __restrict__ out, int n)
{
    __shared__ float b1[1024], b2[64], b3[4];
    const int tid = threadIdx.x;

    if (n <= 16) {
        if (tid == 0) {
            float acc = 0.0f;
            for (int i = 0; i < n; i++) { acc = __fadd_rn(acc, in[i]); out[i] = acc; }
        }
        return;
    }

    const int m1 = (n + 15) >> 4;
    for (int q = tid; q < m1; q += 1024) {
        const int base = q << 4, lim = min(16, n - base);
        float acc = 0.0f;
        if (lim == 16) {
            const float4* in4 = reinterpret_cast<const float4*>(in + base);
            #pragma unroll
            for (int t = 0; t < 4; t++) {
                const float4 v = in4[t];
                acc = __fadd_rn(acc, v.x); acc = __fadd_rn(acc, v.y);
                acc = __fadd_rn(acc, v.z); acc = __fadd_rn(acc, v.w);
            }
        } else {
            for (int k = 0; k < lim; k++) acc = __fadd_rn(acc, in[base + k]);
        }
        b1[q] = acc;
    }
    __syncthreads();

    if (m1 <= 16) {
        if (tid == 0) seq_scan(b1, m1);
        __syncthreads();
    } else {
        const int m2 = (m1 + 15) >> 4;
        if (tid < m2) {
            const int base = tid << 4, lim = min(16, m1 - base);
            float acc = 0.0f;
            for (int k = 0; k < lim; k++) acc = __fadd_rn(acc, b1[base + k]);
            b2[tid] = acc;
        }
        __syncthreads();
        if (m2 <= 16) {
            if (tid == 0) seq_scan(b2, m2);
            __syncthreads();
        } else {
            const int m3 = (m2 + 15) >> 4;      // <= 4
            if (tid < m3) {
                const int base = tid << 4, lim = min(16, m2 - base);
                float acc = 0.0f;
                for (int k = 0; k < lim; k++) acc = __fadd_rn(acc, b2[base + k]);
                b3[tid] = acc;
            }
            __syncthreads();
            if (tid == 0) seq_scan(b3, m3);
            __syncthreads();
            if (tid < m3) {
                const int base = tid << 4, lim = min(16, m2 - base);
                float acc = 0.0f;
                const float p = (tid > 0) ? b3[tid - 1] : 0.0f;
                for (int k = 0; k < lim; k++) {
                    acc = __fadd_rn(acc, b2[base + k]);
                    b2[base + k] = (tid == 0) ? acc : __fadd_rn(acc, p);
                }
            }
            __syncthreads();
        }
        if (tid < m2) {
            const int base = tid << 4, lim = min(16, m1 - base);
            float acc = 0.0f;
            const float p = (tid > 0) ? b2[tid - 1] : 0.0f;
            for (int k = 0; k < lim; k++) {
                acc = __fadd_rn(acc, b1[base + k]);
                b1[base + k] = (tid == 0) ? acc : __fadd_rn(acc, p);
            }
        }
        __syncthreads();
    }
    for (int q = tid; q < m1; q += 1024) {
        const int base = q << 4, lim = min(16, n - base);
        float acc = 0.0f;
        const float p = (q > 0) ? b1[q - 1] : 0.0f;
        for (int k = 0; k < lim; k++) {
            acc = __fadd_rn(acc, in[base + k]);
            out[base + k] = (q == 0) ? acc : __fadd_rn(acc, p);
        }
    }
}

// ---------------------------------------------------------------------------
// K4b: l1s[r] = foldleft(l1[16q .. r]) (+ l2s[q-1] if q>0)  — exact k4
// bracketing. Small kernel (1 MB), barrier is fine here.
// ---------------------------------------------------------------------------
__global__ __launch_bounds__(256)
void k4b_scan_l1(int n1)
{
    __shared__ float sm[256];
    const int tid = threadIdx.x;
    const int r = blockIdx.x * 256 + tid;
    sm[tid] = (r < n1) ? g_l1[r] : 0.0f;
    __syncthreads();
    if (r >= n1) return;
    const int q = r >> 4;
    const int j = r & 15;
    const int rowlocal = tid & ~15;
    float acc = 0.0f;
    for (int k = 0; k <= j; k++)
        acc = __fadd_rn(acc, sm[rowlocal + k]);
    g_l1s[r] = (q == 0) ? acc : __fadd_rn(acc, __ldg(g_l2s + q - 1));
}

// ---------------------------------------------------------------------------
// K5: final downsweep — pure streaming. Prefix p = l1s[r-1], one coalesced
// load issued alongside the float4 sd/id loads. No fold, no barrier.
// Also: segment bounds + per-ray e_lead.
// ---------------------------------------------------------------------------
__global__ __launch_bounds__(256)
void k5_down0_bounds(const int* __restrict__ idx, int S)
{
    const int r    = blockIdx.x * blockDim.x + threadIdx.x;
    const int lane = threadIdx.x & 31;
    const int R    = (S + 15) >> 4;
    if (r >= R) return;
    const int base = r << 4;
    const int lim  = min(16, S - base);

    const float p = (r > 0) ? __ldg(g_l1s + r - 1) : 0.0f;

    float sd[16]; int id[16];
    if (lim == 16) {
        const float4* sd4 = reinterpret_cast<const float4*>(g_sdt + base);
        const int4*   id4 = reinterpret_cast<const int4*>(idx + base);
        #pragma unroll
        for (int q = 0; q < 4; q++) {
            const float4 v = sd4[q];
            sd[4*q+0] = v.x; sd[4*q+1] = v.y; sd[4*q+2] = v.z; sd[4*q+3] = v.w;
            const int4 d = id4[q];
            id[4*q+0] = d.x; id[4*q+1] = d.y; id[4*q+2] = d.z; id[4*q+3] = d.w;
        }
    } else {
        #pragma unroll
        for (int k = 0; k < 16; k++) { sd[k] = 0.0f; id[k] = -1; }
        for (int k = 0; k < lim; k++) { sd[k] = g_sdt[base + k]; id[k] = idx[base + k]; }
    }

    // prev index: neighbor lane's id[15] (same warp), else one scalar load.
    const int nb = __shfl_up_sync(0xffffffffu, id[15], 1);
    int prev = (lane > 0) ? nb
             : (base > 0) ? __ldg(idx + base - 1) : -1;

    float cv[16];
    float acc = 0.0f;
    #pragma unroll
    for (int k = 0; k < 16; k++) {
        if (k < lim) {
            acc = __fadd_rn(acc, sd[k]);
            cv[k] = (r == 0) ? acc : __fadd_rn(acc, p);
        }
    }

    #pragma unroll
    for (int k = 0; k < 16; k++) {
        if (k < lim) {
            const int cur = id[k];
            if (cur != prev) {
                const int i = base + k;
                g_rs[cur] = i;
                if (prev >= 0) g_re[prev] = i;
                g_elead[cur] = __fsub_rn(cv[k], sd[k]);
            }
            prev = cur;
        }
    }
    if (base + lim == S) g_re[prev] = S;

    if (lim == 16) {
        float4* c4 = reinterpret_cast<float4*>(g_c + base);
        #pragma unroll
        for (int q = 0; q < 4; q++)
            c4[q] = make_float4(cv[4*q+0], cv[4*q+1], cv[4*q+2], cv[4*q+3]);
    } else {
        for (int k = 0; k < lim; k++) g_c[base + k] = cv[k];
    }
}

// ---------------------------------------------------------------------------
// K6: warp-per-ray render + accumulate (bounds + e_lead precomputed).
// Scalar hdr loads — independent LDGs pipeline across chunks (R7-proven).
// ---------------------------------------------------------------------------
__global__ __launch_bounds__(K6_THREADS)
void k6_render(const float* __restrict__ hdr,
               float*       __restrict__ out,
               int n_rays)
{
    const int r    = blockIdx.x * WARPS_PER_BLOCK + (threadIdx.x >> 5);
    const int lane = threadIdx.x & 31;
    if (r >= n_rays) return;

    int b = 0;
    float el = 0.0f;
    if (lane == 0)      { b = g_rs[r]; el = g_elead[r]; }
    else if (lane == 1)   b = g_re[r];
    const int start = __shfl_sync(0xffffffffu, b, 0);
    const int end   = __shfl_sync(0xffffffffu, b, 1);

    if (end <= start) {
        if (lane == 0)
            reinterpret_cast<float4*>(out)[r] = make_float4(0.f, 0.f, 0.f, 0.f);
        return;
    }
    const float e_lead = __shfl_sync(0xffffffffu, el, 0);

    float opac = 0.0f, cr = 0.0f, cg = 0.0f, cb = 0.0f;

    for (int base = start; base < end; base += 32) {
        const int i = base + lane;
        if (i < end) {
            const float s  = __ldg(g_sdt + i);
            const float ci = __ldg(g_c + i);
            const float d  = __fsub_rn(__fsub_rn(ci, s), e_lead);
            const float trans = expf(-d);
            const float alpha = 1.0f - expf(-s);
            const float w = __fmul_rn(trans, alpha);
            const long hoff = 3l * i;
            opac += w;
            cr += w * __ldg(hdr + hoff + 0);
            cg += w * __ldg(hdr + hoff + 1);
            cb += w * __ldg(hdr + hoff + 2);
        }
    }

    #pragma unroll
    for (int o = 16; o > 0; o >>= 1) {
        opac += __shfl_xor_sync(0xffffffffu, opac, o);
        cr   += __shfl_xor_sync(0xffffffffu, cr,   o);
        cg   += __shfl_xor_sync(0xffffffffu, cg,   o);
        cb   += __shfl_xor_sync(0xffffffffu, cb,   o);
    }

    if (lane == 0)
        reinterpret_cast<float4*>(out)[r] = make_float4(opac, cr, cg, cb);
}

// ---------------------------------------------------------------------------
extern "C" void kernel_launch(void* const* d_in, const int* in_sizes, int n_in,
                              void* d_out, int out_size)
{
    const float* t_starts    = (const float*)d_in[0];
    const float* t_ends      = (const float*)d_in[1];
    const float* sigmas      = (const float*)d_in[2];
    const float* hdr         = (const float*)d_in[3];
    const int*   ray_indices = (const int*)  d_in[4];
    float*       out         = (float*)d_out;

    const int S      = in_sizes[0];
    const int n_rays = out_size / 4;

    const int n1 = (S + 15) >> 4;
    const int n2 = (n1 + 15) >> 4;

    float *l2 = nullptr, *l2s = nullptr;
    cudaGetSymbolAddress((void**)&l2,  g_l2);
    cudaGetSymbolAddress((void**)&l2s, g_l2s);

    const int T = 256;
    const int g1 = (n1 + T - 1) / T;
    k1_sdt_fold<<<g1, T>>>(t_starts, t_ends, sigmas, S, n_rays);

    k3_midscan<<<1, 1024>>>(l2, l2s, n2);

    k4b_scan_l1<<<g1, T>>>(n1);

    k5_down0_bounds<<<g1, T>>>(ray_indices, S);

    const int blocks = (n_rays + WARPS_PER_BLOCK - 1) / WARPS_PER_BLOCK;
    k6_render<<<blocks, K6_THREADS>>>(hdr, out, n_rays);
}

// round 12
// speedup vs baseline: 1.8369x; 1.8369x over previous
#include <cuda_runtime.h>
#include <cuda_bf16.h>

// NeRF render + accumulate, bit-matching XLA:CPU's ReduceWindowRewriter
// (base_length=16) radix-16 cumsum tree. PASSES @ rel_err 1.5e-7.
// R11: exact R7 champion structure (82.4us). Only k5 changed: named vector
// registers + per-group processing instead of indexed sd[16]/id[16] arrays,
// eliminating local-memory spills (suspected cause of the R8-R10 k5 decay).
// Rounding-critical sequences unchanged:
//   sdt_i = fmul(sigma_i, fsub(te_i, ts_i))
//   fold-left rows with fadd; c = (row0) ? acc : fadd(acc, prefix)
//   excl = fsub(c, sdt); d = fsub(excl_i, e_lead); w = fmul(exp(-d), 1-exp(-sdt))

#define MAX_S    (1 << 22)
#define N1_MAX   (MAX_S / 16)      // 262144
#define N2_MAX   (N1_MAX / 16)     // 16384
#define MAX_RAYS (1 << 18)
#define WARPS_PER_BLOCK 8
#define K6_THREADS (WARPS_PER_BLOCK * 32)

__device__ __align__(16) float g_sdt[MAX_S];
__device__ __align__(16) float g_c[MAX_S];
__device__ __align__(16) float g_l1[N1_MAX];
__device__ __align__(16) float g_l2[N2_MAX];     // raw row totals of l1
__device__ __align__(16) float g_l2s[N2_MAX];    // scanned l2
__device__ int   g_rs[MAX_RAYS];
__device__ int   g_re[MAX_RAYS];
__device__ float g_elead[MAX_RAYS];

// ---------------------------------------------------------------------------
// K1: sdt = fmul(sg, fsub(te, ts)); fold-left per 16-row -> g_l1.
// Also zero-inits ray bounds. (R7 version, unchanged.)
// ---------------------------------------------------------------------------
__global__ __launch_bounds__(256)
void k1_sdt_fold(const float* __restrict__ ts,
                 const float* __restrict__ te,
                 const float* __restrict__ sg,
                 int S, int n_rays)
{
    const int r = blockIdx.x * blockDim.x + threadIdx.x;
    const int R = (S + 15) >> 4;

    for (int j = r; j < n_rays; j += gridDim.x * blockDim.x) { g_rs[j] = 0; g_re[j] = 0; }

    if (r >= R) return;
    const int base = r << 4;

    if (base + 16 <= S) {
        const float4* ts4 = reinterpret_cast<const float4*>(ts + base);
        const float4* te4 = reinterpret_cast<const float4*>(te + base);
        const float4* sg4 = reinterpret_cast<const float4*>(sg + base);
        float4*       sd4 = reinterpret_cast<float4*>(g_sdt + base);
        float acc = 0.0f;
        #pragma unroll
        for (int q = 0; q < 4; q++) {
            const float4 a = ts4[q], b = te4[q], s = sg4[q];
            float4 v;
            v.x = __fmul_rn(s.x, __fsub_rn(b.x, a.x));
            v.y = __fmul_rn(s.y, __fsub_rn(b.y, a.y));
            v.z = __fmul_rn(s.z, __fsub_rn(b.z, a.z));
            v.w = __fmul_rn(s.w, __fsub_rn(b.w, a.w));
            sd4[q] = v;
            acc = __fadd_rn(acc, v.x);   // exact fold-left order preserved
            acc = __fadd_rn(acc, v.y);
            acc = __fadd_rn(acc, v.z);
            acc = __fadd_rn(acc, v.w);
        }
        g_l1[r] = acc;
    } else {
        const int lim = S - base;
        float acc = 0.0f;
        for (int k = 0; k < lim; k++) {
            const int i = base + k;
            const float v = __fmul_rn(sg[i], __fsub_rn(te[i], ts[i]));
            g_sdt[i] = v;
            acc = __fadd_rn(acc, v);
        }
        g_l1[r] = acc;
    }
}

// ---------------------------------------------------------------------------
// K2: fold l1 rows (16) -> l2 raw totals. float4 loads. (R7, unchanged.)
// ---------------------------------------------------------------------------
__global__ __launch_bounds__(256)
void k2_fold(const float* __restrict__ in, int n, float* __restrict__ out)
{
    const int r = blockIdx.x * blockDim.x + threadIdx.x;
    const int R = (n + 15) >> 4;
    if (r >= R) return;
    const int base = r << 4;
    float acc = 0.0f;
    if (base + 16 <= n) {
        const float4* in4 = reinterpret_cast<const float4*>(in + base);
        #pragma unroll
        for (int q = 0; q < 4; q++) {
            const float4 v = in4[q];
            acc = __fadd_rn(acc, v.x);
            acc = __fadd_rn(acc, v.y);
            acc = __fadd_rn(acc, v.z);
            acc = __fadd_rn(acc, v.w);
        }
    } else {
        const int lim = n - base;
        for (int k = 0; k < lim; k++) acc = __fadd_rn(acc, in[base + k]);
    }
    out[r] = acc;
}

// ---------------------------------------------------------------------------
// K3: single-CTA exact radix-16 scan: out = cum(in), n <= 16384. (R7.)
// ---------------------------------------------------------------------------
__device__ __forceinline__ void seq_scan(float* a, int n) {
    float acc = 0.0f;
    for (int i = 0; i < n; i++) { acc = __fadd_rn(acc, a[i]); a[i] = acc; }
}

__global__ __launch_bounds__(1024)
void k3_midscan(const float* __restrict__ in, float* __restrict__ out, int n)
{
    __shared__ float b1[1024], b2[64], b3[4];
    const int tid = threadIdx.x;

    if (n <= 16) {
        if (tid == 0) {
            float acc = 0.0f;
            for (int i = 0; i < n; i++) { acc = __fadd_rn(acc, in[i]); out[i] = acc; }
        }
        return;
    }

    const int m1 = (n + 15) >> 4;
    for (int q = tid; q < m1; q += 1024) {
        const int base = q << 4, lim = min(16, n - base);
        float acc = 0.0f;
        if (lim == 16) {
            const float4* in4 = reinterpret_cast<const float4*>(in + base);
            #pragma unroll
            for (int t = 0; t < 4; t++) {
                const float4 v = in4[t];
                acc = __fadd_rn(acc, v.x); acc = __fadd_rn(acc, v.y);
                acc = __fadd_rn(acc, v.z); acc = __fadd_rn(acc, v.w);
            }
        } else {
            for (int k = 0; k < lim; k++) acc = __fadd_rn(acc, in[base + k]);
        }
        b1[q] = acc;
    }
    __syncthreads();

    if (m1 <= 16) {
        if (tid == 0) seq_scan(b1, m1);
        __syncthreads();
    } else {
        const int m2 = (m1 + 15) >> 4;
        if (tid < m2) {
            const int base = tid << 4, lim = min(16, m1 - base);
            float acc = 0.0f;
            for (int k = 0; k < lim; k++) acc = __fadd_rn(acc, b1[base + k]);
            b2[tid] = acc;
        }
        __syncthreads();
        if (m2 <= 16) {
            if (tid == 0) seq_scan(b2, m2);
            __syncthreads();
        } else {
            const int m3 = (m2 + 15) >> 4;      // <= 4
            if (tid < m3) {
                const int base = tid << 4, lim = min(16, m2 - base);
                float acc = 0.0f;
                for (int k = 0; k < lim; k++) acc = __fadd_rn(acc, b2[base + k]);
                b3[tid] = acc;
            }
            __syncthreads();
            if (tid == 0) seq_scan(b3, m3);
            __syncthreads();
            if (tid < m3) {
                const int base = tid << 4, lim = min(16, m2 - base);
                float acc = 0.0f;
                const float p = (tid > 0) ? b3[tid - 1] : 0.0f;
                for (int k = 0; k < lim; k++) {
                    acc = __fadd_rn(acc, b2[base + k]);
                    b2[base + k] = (tid == 0) ? acc : __fadd_rn(acc, p);
                }
            }
            __syncthreads();
        }
        if (tid < m2) {
            const int base = tid << 4, lim = min(16, m1 - base);
            float acc = 0.0f;
            const float p = (tid > 0) ? b2[tid - 1] : 0.0f;
            for (int k = 0; k < lim; k++) {
                acc = __fadd_rn(acc, b1[base + k]);
                b1[base + k] = (tid == 0) ? acc : __fadd_rn(acc, p);
            }
        }
        __syncthreads();
    }
    for (int q = tid; q < m1; q += 1024) {
        const int base = q << 4, lim = min(16, n - base);
        float acc = 0.0f;
        const float p = (q > 0) ? b1[q - 1] : 0.0f;
        for (int k = 0; k < lim; k++) {
            acc = __fadd_rn(acc, in[base + k]);
            out[base + k] = (q == 0) ? acc : __fadd_rn(acc, p);
        }
    }
}

// ---------------------------------------------------------------------------
// K5: final downsweep (R7 prefix logic) — spill-free layout: named float4/
// int4 registers, each 4-sample group processed to completion. No indexed
// per-thread arrays anywhere.
// ---------------------------------------------------------------------------
__device__ __forceinline__ void k5_group(const float4 s, const int4 d, const int i0,
                                         const bool r0, const float p,
                                         float& acc, int& prev, float4& cv)
{
    acc = __fadd_rn(acc, s.x); cv.x = r0 ? acc : __fadd_rn(acc, p);
    acc = __fadd_rn(acc, s.y); cv.y = r0 ? acc : __fadd_rn(acc, p);
    acc = __fadd_rn(acc, s.z); cv.z = r0 ? acc : __fadd_rn(acc, p);
    acc = __fadd_rn(acc, s.w); cv.w = r0 ? acc : __fadd_rn(acc, p);

    if (d.x != prev) { g_rs[d.x] = i0;     if (prev >= 0) g_re[prev] = i0;     g_elead[d.x] = __fsub_rn(cv.x, s.x); }
    prev = d.x;
    if (d.y != prev) { g_rs[d.y] = i0 + 1; g_re[prev] = i0 + 1; g_elead[d.y] = __fsub_rn(cv.y, s.y); }
    prev = d.y;
    if (d.z != prev) { g_rs[d.z] = i0 + 2; g_re[prev] = i0 + 2; g_elead[d.z] = __fsub_rn(cv.z, s.z); }
    prev = d.z;
    if (d.w != prev) { g_rs[d.w] = i0 + 3; g_re[prev] = i0 + 3; g_elead[d.w] = __fsub_rn(cv.w, s.w); }
    prev = d.w;
}

__global__ __launch_bounds__(256)
void k5_down0_bounds(const int* __restrict__ idx, int S)
{
    const int r = blockIdx.x * blockDim.x + threadIdx.x;
    const int R = (S + 15) >> 4;
    if (r >= R) return;
    const int base = r << 4;
    const int lim  = min(16, S - base);

    // Prefix p = scanned_l1[r-1] (k4 bracketing; R7-proven code path).
    float p = 0.0f;
    if (r != 0) {
        const int q = r >> 4, j = r & 15;
        if (j > 0) {
            const int rowb = q << 4;
            float pl1 = 0.0f;
            for (int k = 0; k < j; k++)                    // fold-left, j terms
                pl1 = __fadd_rn(pl1, __ldg(g_l1 + rowb + k));
            p = (q == 0) ? pl1 : __fadd_rn(pl1, __ldg(g_l2s + q - 1));
        } else {
            p = (q == 1) ? __ldg(g_l2 + 0)
                         : __fadd_rn(__ldg(g_l2 + q - 1), __ldg(g_l2s + q - 2));
        }
    }

    int prev = (base > 0) ? __ldg(idx + base - 1) : -1;
    const bool r0 = (r == 0);

    if (lim == 16) {
        const float4* sd4 = reinterpret_cast<const float4*>(g_sdt + base);
        const int4*   id4 = reinterpret_cast<const int4*>(idx + base);
        // Issue all loads up front (named registers — no spillable arrays).
        const float4 s0 = sd4[0], s1 = sd4[1], s2 = sd4[2], s3 = sd4[3];
        const int4   d0 = id4[0], d1 = id4[1], d2 = id4[2], d3 = id4[3];
        float4* c4 = reinterpret_cast<float4*>(g_c + base);

        float acc = 0.0f;
        float4 cv;
        k5_group(s0, d0, base +  0, r0, p, acc, prev, cv); c4[0] = cv;
        k5_group(s1, d1, base +  4, r0, p, acc, prev, cv); c4[1] = cv;
        k5_group(s2, d2, base +  8, r0, p, acc, prev, cv); c4[2] = cv;
        k5_group(s3, d3, base + 12, r0, p, acc, prev, cv); c4[3] = cv;

        if (base + 16 == S) g_re[prev] = S;
    } else {
        float acc = 0.0f;
        for (int k = 0; k < lim; k++) {
            const int i = base + k;
            const float s = g_sdt[i];
            acc = __fadd_rn(acc, s);
            const float c = r0 ? acc : __fadd_rn(acc, p);
            g_c[i] = c;
            const int cur = idx[i];
            if (cur != prev) {
                g_rs[cur] = i;
                if (prev >= 0) g_re[prev] = i;
                g_elead[cur] = __fsub_rn(c, s);
            }
            prev = cur;
        }
        g_re[prev] = S;
    }
}

// ---------------------------------------------------------------------------
// K6: warp-per-ray render + accumulate (R7, unchanged).
// ---------------------------------------------------------------------------
__global__ __launch_bounds__(K6_THREADS)
void k6_render(const float* __restrict__ hdr,
               float*       __restrict__ out,
               int n_rays)
{
    const int r    = blockIdx.x * WARPS_PER_BLOCK + (threadIdx.x >> 5);
    const int lane = threadIdx.x & 31;
    if (r >= n_rays) return;

    int b = 0;
    float el = 0.0f;
    if (lane == 0)      { b = g_rs[r]; el = g_elead[r]; }
    else if (lane == 1)   b = g_re[r];
    const int start = __shfl_sync(0xffffffffu, b, 0);
    const int end   = __shfl_sync(0xffffffffu, b, 1);

    if (end <= start) {
        if (lane == 0)
            reinterpret_cast<float4*>(out)[r] = make_float4(0.f, 0.f, 0.f, 0.f);
        return;
    }
    const float e_lead = __shfl_sync(0xffffffffu, el, 0);

    float opac = 0.0f, cr = 0.0f, cg = 0.0f, cb = 0.0f;

    for (int base = start; base < end; base += 32) {
        const int i = base + lane;
        if (i < end) {
            const float s  = __ldg(g_sdt + i);
            const float ci = __ldg(g_c + i);
            const float d  = __fsub_rn(__fsub_rn(ci, s), e_lead);
            const float trans = expf(-d);
            const float alpha = 1.0f - expf(-s);
            const float w = __fmul_rn(trans, alpha);
            const long hoff = 3l * i;
            opac += w;
            cr += w * __ldg(hdr + hoff + 0);
            cg += w * __ldg(hdr + hoff + 1);
            cb += w * __ldg(hdr + hoff + 2);
        }
    }

    #pragma unroll
    for (int o = 16; o > 0; o >>= 1) {
        opac += __shfl_xor_sync(0xffffffffu, opac, o);
        cr   += __shfl_xor_sync(0xffffffffu, cr,   o);
        cg   += __shfl_xor_sync(0xffffffffu, cg,   o);
        cb   += __shfl_xor_sync(0xffffffffu, cb,   o);
    }

    if (lane == 0)
        reinterpret_cast<float4*>(out)[r] = make_float4(opac, cr, cg, cb);
}

// ---------------------------------------------------------------------------
extern "C" void kernel_launch(void* const* d_in, const int* in_sizes, int n_in,
                              void* d_out, int out_size)
{
    const float* t_starts    = (const float*)d_in[0];
    const float* t_ends      = (const float*)d_in[1];
    const float* sigmas      = (const float*)d_in[2];
    const float* hdr         = (const float*)d_in[3];
    const int*   ray_indices = (const int*)  d_in[4];
    float*       out         = (float*)d_out;

    const int S      = in_sizes[0];
    const int n_rays = out_size / 4;

    const int n1 = (S + 15) >> 4;
    const int n2 = (n1 + 15) >> 4;

    float *l1 = nullptr, *l2 = nullptr, *l2s = nullptr;
    cudaGetSymbolAddress((void**)&l1,  g_l1);
    cudaGetSymbolAddress((void**)&l2,  g_l2);
    cudaGetSymbolAddress((void**)&l2s, g_l2s);

    const int T = 256;
    k1_sdt_fold<<<(n1 + T - 1) / T, T>>>(t_starts, t_ends, sigmas, S, n_rays);

    if (n1 <= 16) {
        k3_midscan<<<1, 1024>>>(l1, l2s, n1);
        k2_fold<<<1, T>>>(l1, n1, l2);
    } else {
        k2_fold<<<(n2 + T - 1) / T, T>>>(l1, n1, l2);
        k3_midscan<<<1, 1024>>>(l2, l2s, n2);
    }

    k5_down0_bounds<<<(n1 + T - 1) / T, T>>>(ray_indices, S);

    const int blocks = (n_rays + WARPS_PER_BLOCK - 1) / WARPS_PER_BLOCK;
    k6_render<<<blocks, K6_THREADS>>>(hdr, out, n_rays);
}